// round 9
// baseline (speedup 1.0000x reference)
#include <cuda_runtime.h>

#define B   2
#define NQ  900
#define HW  256      // 16*16 argmax domain
#define E   256      // embed dim
#define NH  8        // heads
#define MAXD2 451    // dx^2+dy^2, dx,dy in [-15,15] -> max 450
#define PAIR_GRID (B * HW)          // 512 blocks
#define LUT_BLOCKS 113              // 113*8 warps = 904 >= 902 LUT entries

// Scratch (no allocations allowed -> __device__ globals). SELF-CLEANING:
// the last LUT block re-zeroes g_cnt/g_p/tickets, so every graph replay
// starts from the zero state (first run: static zero-init).
__device__ unsigned char g_cell[B * NQ];    // argmax cell index per (b,q)
__device__ int           g_cnt[B * HW];     // cell histogram per batch
__device__ int           g_p[B * MAXD2];    // pair-count histogram over d2 (EXACT)
__device__ float         g_lut[B * MAXD2];  // bias_mean as function of integer d2
__device__ unsigned int  g_ticket;          // pair-phase completion counter
__device__ unsigned int  g_ticket2;         // mean-phase completion counter

#if defined(__CUDA_ARCH__) && (__CUDA_ARCH__ >= 900)
#define GRID_DEP_SYNC() cudaGridDependencySynchronize()
#else
#define GRID_DEP_SYNC()
#endif

// ---------------------------------------------------------------------------
// Kernel 1: per-(b,q) argmax over 256 values (one warp each), first-index
// tiebreak to match jnp.argmax. Builds the cell histogram. float4 loads.
// ---------------------------------------------------------------------------
__global__ void k_argmax(const float* __restrict__ rp) {
    int gw   = (blockIdx.x * blockDim.x + threadIdx.x) >> 5;
    int lane = threadIdx.x & 31;
    if (gw >= B * NQ) return;

    const float4* p4 = (const float4*)(rp + (size_t)gw * HW);
    float4 va = p4[lane];        // indices 4*lane .. 4*lane+3
    float4 vb = p4[lane + 32];   // indices 128+4*lane .. +3

    float best = -__int_as_float(0x7f800000); // -inf
    int   bi   = 0;
    float v[8] = {va.x, va.y, va.z, va.w, vb.x, vb.y, vb.z, vb.w};
    #pragma unroll
    for (int k = 0; k < 8; k++) {
        int i = (k < 4 ? 4 * lane + k : 128 + 4 * lane + (k - 4));
        if (v[k] > best) { best = v[k]; bi = i; }   // in-lane ascending -> first max
    }
    #pragma unroll
    for (int off = 16; off; off >>= 1) {
        float ov = __shfl_down_sync(0xffffffffu, best, off);
        int   oi = __shfl_down_sync(0xffffffffu, bi,   off);
        if (ov > best || (ov == best && oi < bi)) { best = ov; bi = oi; }
    }
    if (lane == 0) {
        g_cell[gw] = (unsigned char)bi;
        atomicAdd(&g_cnt[(gw / NQ) * HW + bi], 1);
    }
}

// ---------------------------------------------------------------------------
// Kernel 2 (FUSED pair + mean + LUT):
//   * All 512 blocks: pair-count histogram over integer d2 (block = (b,k),
//     thread = l). Exact integer math.
//   * Blocks >= LUT_BLOCKS exit after flushing their contribution.
//   * Blocks < LUT_BLOCKS spin on the ticket until all 512 have flushed
//     (co-residency: 512 blocks x 256 thr fit in wave 1 -> no deadlock),
//     then each redundantly computes both batch means (fp64, fixed order,
//     bit-identical across blocks) and its 8 warps produce 8 LUT entries:
//       LUT[b][d2] = sum_e relu(t*w1[e]+b1[e])*mean_h(w2[e,h]) + mean_h(b2),
//       t = (sqrt(d2)/15)/(mean[b]+1e-6)
//   * Second ticket: last mean-reader block zeroes all scratch.
// ---------------------------------------------------------------------------
__global__ void __launch_bounds__(256) k_pairlut(
    const float* __restrict__ w1, const float* __restrict__ b1,
    const float* __restrict__ w2, const float* __restrict__ b2)
{
    __shared__ int    sP[MAXD2];
    __shared__ int    sCnt[HW];
    __shared__ double sRed[256];
    __shared__ float  sMean[B];
    __shared__ bool   sLast;

    const int  t        = threadIdx.x;
    const int  wid      = t >> 5;
    const int  lane     = t & 31;
    const int  b        = blockIdx.x >> 8;
    const int  k        = blockIdx.x & 255;
    const bool lutBlock = blockIdx.x < LUT_BLOCKS;

    // ---- PDL prologue: LUT weights (pure inputs; overlap k_argmax) ----
    float w1r[8], b1r[8], wsr[8], bm = 0.f;
    if (lutBlock) {
        #pragma unroll
        for (int kk = 0; kk < 8; kk++) {
            int i = lane + kk * 32;
            w1r[kk] = w1[i];
            b1r[kk] = b1[i];
            const float4* w2r = (const float4*)(w2 + i * NH);
            float4 wa = w2r[0], wb = w2r[1];
            wsr[kk] = ((wa.x + wa.y) + (wa.z + wa.w) +
                       (wb.x + wb.y) + (wb.z + wb.w)) * (1.0f / NH);
        }
        #pragma unroll
        for (int h = 0; h < NH; h++) bm += b2[h];
        bm *= (1.0f / NH);
    }
    sP[t] = 0;
    if (t + 256 < MAXD2) sP[t + 256] = 0;

    GRID_DEP_SYNC();                    // wait for k_argmax's g_cnt

    // ---- pair phase ----
    sCnt[t] = g_cnt[b * HW + t];
    __syncthreads();
    {
        int ck = sCnt[k];
        if (ck) {
            int cl = sCnt[t];
            if (cl) {
                int dx = (k & 15) - (t & 15);
                int dy = (k >> 4) - (t >> 4);
                atomicAdd(&sP[dx * dx + dy * dy], ck * cl);
            }
        }
    }
    __syncthreads();
    {
        int v = sP[t];
        if (v) atomicAdd(&g_p[b * MAXD2 + t], v);
        if (t + 256 < MAXD2) {
            v = sP[t + 256];
            if (v) atomicAdd(&g_p[b * MAXD2 + t + 256], v);
        }
    }
    __threadfence();                    // release this block's g_p contribution
    __syncthreads();
    if (t == 0) atomicAdd(&g_ticket, 1u);

    if (!lutBlock) return;              // most blocks exit, freeing SMs

    // ---- spin until all 512 pair contributions are published ----
    if (t == 0) {
        while (*(volatile unsigned int*)&g_ticket < (unsigned)PAIR_GRID)
            __nanosleep(32);
        __threadfence();                // acquire
    }
    __syncthreads();

    // ---- per-batch means (redundant per block; bit-identical) ----
    for (int bb = 0; bb < B; bb++) {
        double acc = (double)g_p[bb * MAXD2 + t] * (double)sqrtf((float)t);
        if (t + 256 < MAXD2)
            acc += (double)g_p[bb * MAXD2 + t + 256] * (double)sqrtf((float)(t + 256));
        sRed[t] = acc;
        __syncthreads();
        for (int s = 128; s; s >>= 1) {
            if (t < s) sRed[t] += sRed[t + s];
            __syncthreads();
        }
        if (t == 0)
            sMean[bb] = (float)(sRed[0] / 15.0 / ((double)NQ * (double)NQ));
        __syncthreads();
    }

    // ---- LUT: one warp per entry ----
    int gwarp = blockIdx.x * 8 + wid;   // 0..903
    if (gwarp < B * MAXD2) {
        int   bb  = gwarp >= MAXD2 ? 1 : 0;
        int   d2  = gwarp - bb * MAXD2;
        float dst = sqrtf((float)d2) * (1.0f / 15.0f);
        float tt  = dst / (sMean[bb] + 1e-6f);

        float acc = 0.f;
        #pragma unroll
        for (int kk = 0; kk < 8; kk++)
            acc = fmaf(fmaxf(fmaf(tt, w1r[kk], b1r[kk]), 0.f), wsr[kk], acc);
        #pragma unroll
        for (int off = 16; off; off >>= 1)
            acc += __shfl_down_sync(0xffffffffu, acc, off);
        if (lane == 0) g_lut[gwarp] = acc + bm;
    }

    // ---- cleanup by the LAST lut block (all means already read g_p) ----
    __syncthreads();
    if (t == 0) {
        __threadfence();
        sLast = (atomicAdd(&g_ticket2, 1u) == (unsigned)(LUT_BLOCKS - 1));
    }
    __syncthreads();
    if (sLast) {
        for (int i = t; i < B * MAXD2; i += 256) g_p[i] = 0;
        g_cnt[t] = 0;
        g_cnt[t + 256] = 0;
        if (t == 0) { g_ticket = 0; g_ticket2 = 0; }
    }
}

// ---------------------------------------------------------------------------
// Kernel 3: out = attn + lam * lut[d2(cell_i, cell_j)].
// 4 rows per block (450 blocks x 512 threads): both float4 loads issued
// back-to-back (MLP_p1=2) in the PDL prologue, before the grid sync.
// ---------------------------------------------------------------------------
__global__ void __launch_bounds__(512) k_out(const float* __restrict__ attn,
                                             const float* __restrict__ lam,
                                             float* __restrict__ out) {
    __shared__ float sLut[MAXD2];

    int t    = threadIdx.x;
    int row0 = blockIdx.x * 4;            // rows row0 .. row0+3 (same batch)
    int b    = row0 >= NQ ? 1 : 0;
    int half = t >> 8;                    // 0/1
    int v    = t & 255;                   // vector index within row
    bool act = v < NQ / 4;                // 225 float4 per row

    int rowA = row0 + half;
    int rowB = row0 + 2 + half;

    // prologue: input-only loads, both in flight before any dependency
    float4 aA = make_float4(0.f, 0.f, 0.f, 0.f);
    float4 aB = aA;
    if (act) {
        aA = *((const float4*)(attn + (size_t)rowA * NQ) + v);
        aB = *((const float4*)(attn + (size_t)rowB * NQ) + v);
    }
    float la = __ldg(lam);

    GRID_DEP_SYNC();                      // wait for g_lut / g_cell

    if (t < MAXD2) sLut[t] = g_lut[b * MAXD2 + t];
    int ciA = g_cell[rowA];
    int ciB = g_cell[rowB];
    uchar4 cj4 = make_uchar4(0, 0, 0, 0);
    if (act) cj4 = *(const uchar4*)(g_cell + b * NQ + v * 4);
    __syncthreads();

    if (!act) return;
    int cjx[4], cjy[4];
    unsigned char cc[4] = {cj4.x, cj4.y, cj4.z, cj4.w};
    #pragma unroll
    for (int k = 0; k < 4; k++) { cjx[k] = cc[k] & 15; cjy[k] = cc[k] >> 4; }

    int cixA = ciA & 15, ciyA = ciA >> 4;
    int cixB = ciB & 15, ciyB = ciB >> 4;

    float avA[4] = {aA.x, aA.y, aA.z, aA.w};
    float avB[4] = {aB.x, aB.y, aB.z, aB.w};
    float rA[4], rB[4];
    #pragma unroll
    for (int k = 0; k < 4; k++) {
        int dxA = cixA - cjx[k], dyA = ciyA - cjy[k];
        int dxB = cixB - cjx[k], dyB = ciyB - cjy[k];
        rA[k] = fmaf(la, sLut[dxA * dxA + dyA * dyA], avA[k]);
        rB[k] = fmaf(la, sLut[dxB * dxB + dyB * dyB], avB[k]);
    }
    *((float4*)(out + (size_t)rowA * NQ) + v) = make_float4(rA[0], rA[1], rA[2], rA[3]);
    *((float4*)(out + (size_t)rowB * NQ) + v) = make_float4(rB[0], rB[1], rB[2], rB[3]);
}

// ---------------------------------------------------------------------------
// Launch: 3 kernels chained with Programmatic Dependent Launch.
// ---------------------------------------------------------------------------
static inline void pdl_cfg(cudaLaunchConfig_t* cfg, cudaLaunchAttribute* attr,
                           dim3 grid, dim3 block) {
    attr->id = cudaLaunchAttributeProgrammaticStreamSerialization;
    attr->val.programmaticStreamSerializationAllowed = 1;
    cfg->gridDim = grid;
    cfg->blockDim = block;
    cfg->dynamicSmemBytes = 0;
    cfg->stream = 0;          // legacy default stream (same as <<<>>>)
    cfg->attrs = attr;
    cfg->numAttrs = 1;
}

extern "C" void kernel_launch(void* const* d_in, const int* in_sizes, int n_in,
                              void* d_out, int out_size) {
    const float* attn = (const float*)d_in[0];
    const float* rp   = (const float*)d_in[1];
    const float* lam  = (const float*)d_in[2];
    const float* w1   = (const float*)d_in[3];
    const float* b1   = (const float*)d_in[4];
    const float* w2   = (const float*)d_in[5];
    const float* b2   = (const float*)d_in[6];
    float*       out  = (float*)d_out;

    // primary
    k_argmax<<<(B * NQ * 32) / 256, 256>>>(rp);   // 225 blocks

    cudaLaunchConfig_t cfg;
    cudaLaunchAttribute attr;

    pdl_cfg(&cfg, &attr, dim3(PAIR_GRID), dim3(256));
    cudaLaunchKernelEx(&cfg, k_pairlut, w1, b1, w2, b2);

    pdl_cfg(&cfg, &attr, dim3(B * NQ / 4), dim3(512));
    cudaLaunchKernelEx(&cfg, k_out, attn, lam, out);
}